// round 6
// baseline (speedup 1.0000x reference)
#include <cuda_runtime.h>

// ---------------- problem constants ----------------
#define DF   64      // feature dim
#define HHn  8       // heads
#define HD   512     // H*D hidden
#define LLn  3       // metapath length
#define E_MAX  100000
#define ND_MAX 50000

// ---------------- tiling constants ----------------
#define BM   32      // edges per block
#define NT   256     // threads per block
#define NC   128     // output columns per chunk
#define KT   16      // k per shared tile
#define WPAD 130     // padded row length of W tile in shared (floats)

// ---------------- device scratch (static, allowed) ----------------
__device__ float g_eft[(size_t)E_MAX * HD];   // final hidden per edge
__device__ float g_aexp[(size_t)E_MAX * HHn]; // exp(leakyrelu(logit))
__device__ float g_asum[(size_t)ND_MAX * HHn];// segment sums

// ---------------- helpers ----------------
__device__ __forceinline__ float2 ffma2(float2 a, float2 b, float2 c) {
    float2 d;
    asm("fma.rn.f32x2 %0, %1, %2, %3;"
        : "=l"(*reinterpret_cast<unsigned long long*>(&d))
        : "l"(*reinterpret_cast<unsigned long long*>(&a)),
          "l"(*reinterpret_cast<unsigned long long*>(&b)),
          "l"(*reinterpret_cast<unsigned long long*>(&c)));
    return d;
}

__device__ __forceinline__ float sigmf(float x) {
    return __fdividef(1.0f, 1.0f + __expf(-x));
}
__device__ __forceinline__ float tanhfast(float x) {
    // tanh(x) = 1 - 2/(e^{2x}+1); saturates correctly at +-1
    return 1.0f - __fdividef(2.0f, __expf(2.0f * x) + 1.0f);
}
__device__ __forceinline__ float2 ld2(const float* p) {
    return *reinterpret_cast<const float2*>(p);
}
__device__ __forceinline__ float2 add2(float2 a, float2 b) {
    return make_float2(a.x + b.x, a.y + b.y);
}

// Accumulate a [BM x NC] x 3-gate GEMM chunk over K, staging W tiles in smem.
// acc groups: 0 = r (combined), 1 = z (combined), NIDX = n-gate target
// (2 for the input path i_n, 3 for the hidden path h_n).
template<int K, int LD, int NIDX>
__device__ __forceinline__ void accum_tiles(
    float2 (&acc)[4][4][2],
    const float* __restrict__ Wsrc,
    const float* inp, int inStride,
    float* sW, int j0, int tid, int eBase, int cg)
{
    for (int kt = 0; kt < K; kt += KT) {
        __syncthreads();
        // stage W tile transposed: sW[(g*KT+kk)*WPAD + col]
        for (int i4 = tid; i4 < 3 * KT * NC / 4; i4 += NT) {
            int kk4  = i4 & 3;
            int colg = (i4 >> 2) & (NC - 1);
            int g    = i4 >> 9;
            float4 v = *reinterpret_cast<const float4*>(
                &Wsrc[(size_t)(g * HD + j0 + colg) * LD + kt + kk4 * 4]);
            int base = (g * KT + kk4 * 4) * WPAD + colg;
            sW[base]            = v.x;
            sW[base + WPAD]     = v.y;
            sW[base + 2 * WPAD] = v.z;
            sW[base + 3 * WPAD] = v.w;
        }
        __syncthreads();
        #pragma unroll
        for (int kk = 0; kk < KT; ++kk) {
            float2 hv[4];
            #pragma unroll
            for (int e = 0; e < 4; ++e) {
                float v = inp[(eBase + e) * inStride + kt + kk];  // smem broadcast
                hv[e] = make_float2(v, v);
            }
            #pragma unroll
            for (int g = 0; g < 3; ++g) {
                const int ai = (g == 2) ? NIDX : g;
                const float* wr = &sW[(g * KT + kk) * WPAD + (cg << 1)];
                float2 wA = ld2(wr);
                float2 wB = ld2(wr + 64);
                #pragma unroll
                for (int e = 0; e < 4; ++e) {
                    acc[ai][e][0] = ffma2(hv[e], wA, acc[ai][e][0]);
                    acc[ai][e][1] = ffma2(hv[e], wB, acc[ai][e][1]);
                }
            }
        }
    }
}

// ---------------- fused gather + GRU + attention-logit kernel ----------------
__global__ void __launch_bounds__(NT, 1)
gru_kernel(const float* __restrict__ feat,
           const float* __restrict__ Wih, const float* __restrict__ Whh,
           const float* __restrict__ bih, const float* __restrict__ bhh,
           const float* __restrict__ attnw,
           const int* __restrict__ mp_idx, const int* __restrict__ dst,
           int E)
{
    extern __shared__ float sm[];
    float* sx = sm;                       // [LLn][BM][DF] = 6144
    float* hA = sm + LLn * BM * DF;       // [BM][HD]      = 16384
    float* hB = hA + BM * HD;             // [BM][HD]      = 16384
    float* sW = hB + BM * HD;             // [3][KT][WPAD] = 6240

    const int tid = threadIdx.x;
    const int e0  = blockIdx.x * BM;

    // gather metapath node features for all 3 steps
    for (int i = tid; i < LLn * BM * DF; i += NT) {
        int t = i / (BM * DF);
        int r = i - t * (BM * DF);
        int e = r >> 6;
        int d = r & 63;
        int ge   = e0 + e;
        int node = (ge < E) ? mp_idx[ge * LLn + t] : 0;
        sx[i] = feat[(size_t)node * DF + d];
    }
    __syncthreads();

    const int eg    = tid >> 5;   // warp id -> edge group
    const int cg    = tid & 31;   // lane    -> column group
    const int eBase = eg << 2;    // 4 edges per thread

    float* hOld = hA;
    float* hNew = hB;

    for (int t = 0; t < LLn; ++t) {
        for (int j0 = 0; j0 < HD; j0 += NC) {
            const int c0 = j0 + (cg << 1);
            float2 acc[4][4][2];
            // init accumulators with biases
            float2 br0 = add2(ld2(&bih[c0]),           ld2(&bhh[c0]));
            float2 br1 = add2(ld2(&bih[c0 + 64]),      ld2(&bhh[c0 + 64]));
            float2 bz0 = add2(ld2(&bih[HD + c0]),      ld2(&bhh[HD + c0]));
            float2 bz1 = add2(ld2(&bih[HD + c0 + 64]), ld2(&bhh[HD + c0 + 64]));
            float2 bi0 = ld2(&bih[2 * HD + c0]);
            float2 bi1 = ld2(&bih[2 * HD + c0 + 64]);
            float2 bh0 = ld2(&bhh[2 * HD + c0]);
            float2 bh1 = ld2(&bhh[2 * HD + c0 + 64]);
            #pragma unroll
            for (int e = 0; e < 4; ++e) {
                acc[0][e][0] = br0; acc[0][e][1] = br1;
                acc[1][e][0] = bz0; acc[1][e][1] = bz1;
                acc[2][e][0] = bi0; acc[2][e][1] = bi1;
                acc[3][e][0] = bh0; acc[3][e][1] = bh1;
            }
            // input-path GEMM (K = 64): r,z into combined accs, n into acc[2]
            accum_tiles<DF, DF, 2>(acc, Wih, sx + t * BM * DF, DF, sW, j0, tid, eBase, cg);
            // hidden-path GEMM (K = 512): r,z combined, n into acc[3]
            if (t > 0)
                accum_tiles<HD, HD, 3>(acc, Whh, hOld, HD, sW, j0, tid, eBase, cg);

            // gate combine + write h_new chunk
            #pragma unroll
            for (int e = 0; e < 4; ++e) {
                const int le = eBase + e;
                #pragma unroll
                for (int p = 0; p < 2; ++p) {
                    const int col = c0 + p * 64;
                    float2 hp = make_float2(0.f, 0.f);
                    if (t > 0) hp = ld2(&hOld[le * HD + col]);
                    float2 R = acc[0][e][p], Z = acc[1][e][p];
                    float2 IN = acc[2][e][p], HN = acc[3][e][p];
                    float2 o;
                    {
                        float r = sigmf(R.x), z = sigmf(Z.x);
                        float n = tanhfast(IN.x + r * HN.x);
                        o.x = n + z * (hp.x - n);
                    }
                    {
                        float r = sigmf(R.y), z = sigmf(Z.y);
                        float n = tanhfast(IN.y + r * HN.y);
                        o.y = n + z * (hp.y - n);
                    }
                    *reinterpret_cast<float2*>(&hNew[le * HD + col]) = o;
                }
            }
        }
        float* tmp = hOld; hOld = hNew; hNew = tmp;
        __syncthreads();
    }

    // ---- epilogue: hOld holds final hidden [BM][HD] ----
    for (int i = tid; i < BM * HD; i += NT) {
        int ge = e0 + (i >> 9);
        if (ge < E) g_eft[(size_t)ge * HD + (i & 511)] = hOld[i];
    }
    {
        int eL   = tid >> 3;   // local edge 0..31
        int hh   = tid & 7;    // head
        int lane = tid & 31;
        float s = 0.f;
        #pragma unroll
        for (int k = 0; k < DF; ++k) {
            int d = (k + (lane << 1)) & 63;  // stagger to reduce bank conflicts
            s += hOld[eL * HD + (hh << 6) + d] * attnw[(hh << 6) + d];
        }
        int ge = e0 + eL;
        if (ge < E) {
            float a  = s > 0.f ? s : 0.01f * s;   // leaky relu
            float ex = __expf(a);                  // softmax numerator (no max-shift; logits bounded)
            g_aexp[ge * HHn + hh] = ex;
            atomicAdd(&g_asum[(size_t)dst[ge] * HHn + hh], ex);
        }
    }
}

// ---------------- init kernel ----------------
__global__ void zero_kernel(float* __restrict__ out, int nOut, int nSum) {
    int stride = gridDim.x * blockDim.x;
    int start  = blockIdx.x * blockDim.x + threadIdx.x;
    for (int i = start; i < nOut; i += stride) out[i] = 0.0f;
    for (int i = start; i < nSum; i += stride) g_asum[i] = 0.0f;
}

// ---------------- finalize: alpha scale + scatter-sum ----------------
__global__ void finalize_kernel(const int* __restrict__ dst,
                                float* __restrict__ out, int E) {
    int idx = blockIdx.x * blockDim.x + threadIdx.x;
    if (idx >= E * HD) return;
    int e  = idx >> 9;
    int c  = idx & (HD - 1);
    int hh = c >> 6;
    int dd = dst[e];
    float alpha = __fdividef(g_aexp[e * HHn + hh], g_asum[dd * HHn + hh]);
    atomicAdd(&out[dd * HD + c], g_eft[idx] * alpha);
}

// ---------------- launcher ----------------
extern "C" void kernel_launch(void* const* d_in, const int* in_sizes, int n_in,
                              void* d_out, int out_size) {
    const float* feat  = (const float*)d_in[0];
    const float* Wih   = (const float*)d_in[1];
    const float* Whh   = (const float*)d_in[2];
    const float* bih   = (const float*)d_in[3];
    const float* bhh   = (const float*)d_in[4];
    const float* attnw = (const float*)d_in[5];
    const int* mp_idx  = (const int*)d_in[6];
    const int* dst     = (const int*)d_in[7];
    const int E  = in_sizes[7];
    float* out = (float*)d_out;
    const int nd8 = (out_size / (HHn * DF)) * HHn;   // ND * H

    size_t smem = (size_t)(LLn * BM * DF + 2 * BM * HD + 3 * KT * WPAD) * sizeof(float);
    cudaFuncSetAttribute(gru_kernel, cudaFuncAttributeMaxDynamicSharedMemorySize, (int)smem);

    zero_kernel<<<2048, 256>>>(out, out_size, nd8);

    int nb = (E + BM - 1) / BM;
    gru_kernel<<<nb, NT, smem>>>(feat, Wih, Whh, bih, bhh, attnw, mp_idx, dst, E);

    int total = E * HD;
    finalize_kernel<<<(total + 255) / 256, 256>>>(dst, out, E);
}

// round 7
// speedup vs baseline: 2.4096x; 2.4096x over previous
#include <cuda_runtime.h>

// ---------------- problem constants ----------------
#define DF    64
#define HHn   8
#define HD    512
#define G3    1536      // 3 * HD
#define NODES_MAX 100000
#define E_MAX     100000
#define ND_MAX    50000

// ---------------- device scratch ----------------
__device__ float g_F [(size_t)NODES_MAX * G3];  // features @ W_ih^T + b_ih   (614 MB)
__device__ float g_h [(size_t)E_MAX * HD];      // per-edge hidden state      (205 MB)
__device__ float g_gh[(size_t)E_MAX * G3];      // h @ W_hh^T + b_hh          (614 MB)
__device__ float g_aexp[(size_t)E_MAX * HHn];
__device__ float g_asum[(size_t)ND_MAX * HHn];

// ---------------- helpers ----------------
__device__ __forceinline__ float2 ffma2(float2 a, float2 b, float2 c) {
    float2 d;
    asm("fma.rn.f32x2 %0, %1, %2, %3;"
        : "=l"(*reinterpret_cast<unsigned long long*>(&d))
        : "l"(*reinterpret_cast<unsigned long long*>(&a)),
          "l"(*reinterpret_cast<unsigned long long*>(&b)),
          "l"(*reinterpret_cast<unsigned long long*>(&c)));
    return d;
}
__device__ __forceinline__ float4 ld4(const float* p) {
    return *reinterpret_cast<const float4*>(p);
}
__device__ __forceinline__ void st4(float* p, float4 v) {
    *reinterpret_cast<float4*>(p) = v;
}
__device__ __forceinline__ float sigmf(float x) {
    return __fdividef(1.0f, 1.0f + __expf(-x));
}
__device__ __forceinline__ float tanhfast(float x) {
    return 1.0f - __fdividef(2.0f, __expf(2.0f * x) + 1.0f);
}
// one GRU gate-combine: i-gates (f*), h-gates (g*, bias already folded), prev h
__device__ __forceinline__ float gru_one(float fr, float gr, float fz, float gz,
                                         float fn, float gn, float hp) {
    float r = sigmf(fr + gr);
    float z = sigmf(fz + gz);
    float n = tanhfast(fn + r * gn);
    return n + z * (hp - n);
}

// ================= SGEMM: C[M,1536] = A[M,K] @ B[1536,K]^T + bias =================
// 128x128 tile, K-tiles of 16, 128 threads, 16(m) x 8(n) register tile (f32x2).
#define MT   128
#define NTW  128
#define KT   16
#define PAD  132
#define TPB  128

template<int K>
__global__ void __launch_bounds__(TPB, 2)
sgemm_bias(const float* __restrict__ A, const float* __restrict__ B,
           const float* __restrict__ bias, float* __restrict__ C, int M)
{
    __shared__ float As[2][KT * PAD];
    __shared__ float Bs[2][KT * PAD];

    const int tid = threadIdx.x;
    const int nb  = blockIdx.x * NTW;
    const int mb  = blockIdx.y * MT;

    const int tx = tid & 15;          // n-group
    const int ty = tid >> 4;          // m-group (0..7)
    const int m0 = ty * 16;
    const int nA = tx * 4;
    const int nB = 64 + tx * 4;

    float4 pa[4], pb[4];
    int ldrow[4], ldkq[4];
    #pragma unroll
    for (int j = 0; j < 4; ++j) {
        int f = tid + j * TPB;        // float4 index 0..511
        ldrow[j] = f >> 2;
        ldkq[j]  = f & 3;
    }

    float2 acc[16][4];
    #pragma unroll
    for (int i = 0; i < 16; ++i)
        #pragma unroll
        for (int j = 0; j < 4; ++j) acc[i][j] = make_float2(0.f, 0.f);

    // prologue: load tile 0
    #pragma unroll
    for (int j = 0; j < 4; ++j) {
        int ar = mb + ldrow[j]; if (ar >= M) ar = M - 1;
        pa[j] = ld4(&A[(size_t)ar * K + ldkq[j] * 4]);
        pb[j] = ld4(&B[(size_t)(nb + ldrow[j]) * K + ldkq[j] * 4]);
    }
    #pragma unroll
    for (int j = 0; j < 4; ++j) {
        float* sA = &As[0][(ldkq[j] * 4) * PAD + ldrow[j]];
        sA[0] = pa[j].x; sA[PAD] = pa[j].y; sA[2*PAD] = pa[j].z; sA[3*PAD] = pa[j].w;
        float* sB = &Bs[0][(ldkq[j] * 4) * PAD + ldrow[j]];
        sB[0] = pb[j].x; sB[PAD] = pb[j].y; sB[2*PAD] = pb[j].z; sB[3*PAD] = pb[j].w;
    }
    __syncthreads();

    const int T = K / KT;
    for (int t = 0; t < T; ++t) {
        const int buf = t & 1;
        if (t + 1 < T) {
            const int kt = (t + 1) * KT;
            #pragma unroll
            for (int j = 0; j < 4; ++j) {
                int ar = mb + ldrow[j]; if (ar >= M) ar = M - 1;
                pa[j] = ld4(&A[(size_t)ar * K + kt + ldkq[j] * 4]);
                pb[j] = ld4(&B[(size_t)(nb + ldrow[j]) * K + kt + ldkq[j] * 4]);
            }
        }
        #pragma unroll
        for (int kk = 0; kk < KT; ++kk) {
            const float* ar = &As[buf][kk * PAD + m0];
            float4 a0 = ld4(ar), a1 = ld4(ar + 4), a2 = ld4(ar + 8), a3 = ld4(ar + 12);
            const float* br = &Bs[buf][kk * PAD];
            float4 b0 = ld4(br + nA);
            float4 b1 = ld4(br + nB);
            float2 b00 = make_float2(b0.x, b0.y), b01 = make_float2(b0.z, b0.w);
            float2 b10 = make_float2(b1.x, b1.y), b11 = make_float2(b1.z, b1.w);
            float av[16] = {a0.x,a0.y,a0.z,a0.w, a1.x,a1.y,a1.z,a1.w,
                            a2.x,a2.y,a2.z,a2.w, a3.x,a3.y,a3.z,a3.w};
            #pragma unroll
            for (int i = 0; i < 16; ++i) {
                float2 aa = make_float2(av[i], av[i]);
                acc[i][0] = ffma2(aa, b00, acc[i][0]);
                acc[i][1] = ffma2(aa, b01, acc[i][1]);
                acc[i][2] = ffma2(aa, b10, acc[i][2]);
                acc[i][3] = ffma2(aa, b11, acc[i][3]);
            }
        }
        __syncthreads();
        if (t + 1 < T) {
            const int nbuf = (t + 1) & 1;
            #pragma unroll
            for (int j = 0; j < 4; ++j) {
                float* sA = &As[nbuf][(ldkq[j] * 4) * PAD + ldrow[j]];
                sA[0] = pa[j].x; sA[PAD] = pa[j].y; sA[2*PAD] = pa[j].z; sA[3*PAD] = pa[j].w;
                float* sB = &Bs[nbuf][(ldkq[j] * 4) * PAD + ldrow[j]];
                sB[0] = pb[j].x; sB[PAD] = pb[j].y; sB[2*PAD] = pb[j].z; sB[3*PAD] = pb[j].w;
            }
            __syncthreads();
        }
    }

    // epilogue: add bias, store
    float4 bsA = ld4(&bias[nb + nA]);
    float4 bsB = ld4(&bias[nb + nB]);
    #pragma unroll
    for (int i = 0; i < 16; ++i) {
        int m = mb + m0 + i;
        if (m < M) {
            float4 v0 = make_float4(acc[i][0].x + bsA.x, acc[i][0].y + bsA.y,
                                    acc[i][1].x + bsA.z, acc[i][1].y + bsA.w);
            float4 v1 = make_float4(acc[i][2].x + bsB.x, acc[i][2].y + bsB.y,
                                    acc[i][3].x + bsB.z, acc[i][3].y + bsB.w);
            st4(&C[(size_t)m * G3 + nb + nA], v0);
            st4(&C[(size_t)m * G3 + nb + nB], v1);
        }
    }
}

// ================= elementwise kernels =================
__global__ void zero_kernel(float* __restrict__ out, int nOut, int nSum) {
    int stride = gridDim.x * blockDim.x;
    int start  = blockIdx.x * blockDim.x + threadIdx.x;
    for (int i = start; i < nOut; i += stride) out[i] = 0.0f;
    for (int i = start; i < nSum; i += stride) g_asum[i] = 0.0f;
}

// step 0: h0 = 0 -> gh = b_hh.  h1 = (1-z) * n
__global__ void step0_kernel(const int* __restrict__ mp,
                             const float* __restrict__ bhh, int E) {
    int i = blockIdx.x * blockDim.x + threadIdx.x;
    if (i >= E * (HD / 4)) return;
    int e  = i >> 7;
    int c4 = (i & 127) << 2;
    int node = mp[e * 3 + 0];
    const float* Fp = &g_F[(size_t)node * G3];
    float4 fr = ld4(Fp + c4), fz = ld4(Fp + 512 + c4), fn = ld4(Fp + 1024 + c4);
    float4 br = ld4(bhh + c4), bz = ld4(bhh + 512 + c4), bn = ld4(bhh + 1024 + c4);
    float4 h;
    h.x = gru_one(fr.x, br.x, fz.x, bz.x, fn.x, bn.x, 0.f);
    h.y = gru_one(fr.y, br.y, fz.y, bz.y, fn.y, bn.y, 0.f);
    h.z = gru_one(fr.z, br.z, fz.z, bz.z, fn.z, bn.z, 0.f);
    h.w = gru_one(fr.w, br.w, fz.w, bz.w, fn.w, bn.w, 0.f);
    st4(&g_h[(size_t)e * HD + c4], h);
}

// steps 1,2: gh (bias folded) in g_gh; h updated in place
__global__ void gates_kernel(const int* __restrict__ mp, int E, int t) {
    int i = blockIdx.x * blockDim.x + threadIdx.x;
    if (i >= E * (HD / 4)) return;
    int e  = i >> 7;
    int c4 = (i & 127) << 2;
    int node = mp[e * 3 + t];
    const float* Fp = &g_F[(size_t)node * G3];
    const float* Gp = &g_gh[(size_t)e * G3];
    float4 fr = ld4(Fp + c4), fz = ld4(Fp + 512 + c4), fn = ld4(Fp + 1024 + c4);
    float4 gr = ld4(Gp + c4), gz = ld4(Gp + 512 + c4), gn = ld4(Gp + 1024 + c4);
    float4 hp = ld4(&g_h[(size_t)e * HD + c4]);
    float4 h;
    h.x = gru_one(fr.x, gr.x, fz.x, gz.x, fn.x, gn.x, hp.x);
    h.y = gru_one(fr.y, gr.y, fz.y, gz.y, fn.y, gn.y, hp.y);
    h.z = gru_one(fr.z, gr.z, fz.z, gz.z, fn.z, gn.z, hp.z);
    h.w = gru_one(fr.w, gr.w, fz.w, gz.w, fn.w, gn.w, hp.w);
    st4(&g_h[(size_t)e * HD + c4], h);
}

// attention logits + exp + segment-sum
__global__ void logit_kernel(const float* __restrict__ attnw,
                             const int* __restrict__ dst, int E) {
    int gid = blockIdx.x * blockDim.x + threadIdx.x;
    if (gid >= E * HHn) return;
    int e = gid >> 3, hh = gid & 7;
    const float* hp = &g_h[(size_t)e * HD + hh * 64];
    const float* ap = &attnw[hh * 64];
    float s = 0.f;
    #pragma unroll
    for (int k = 0; k < 16; ++k) {
        float4 hv = ld4(hp + k * 4);
        float4 av = ld4(ap + k * 4);
        s += hv.x * av.x + hv.y * av.y + hv.z * av.z + hv.w * av.w;
    }
    float a  = s > 0.f ? s : 0.01f * s;
    float ex = __expf(a);   // logits bounded; max-shift unnecessary (validated R5)
    g_aexp[gid] = ex;
    atomicAdd(&g_asum[(size_t)dst[e] * HHn + hh], ex);
}

// alpha scale + scatter-sum into output
__global__ void finalize_kernel(const int* __restrict__ dst,
                                float* __restrict__ out, int E) {
    int i = blockIdx.x * blockDim.x + threadIdx.x;
    if (i >= E * (HD / 4)) return;
    int e  = i >> 7;
    int c4 = (i & 127) << 2;
    int hh = c4 >> 6;
    int dd = dst[e];
    float alpha = __fdividef(g_aexp[e * HHn + hh], g_asum[(size_t)dd * HHn + hh]);
    float4 v = ld4(&g_h[(size_t)e * HD + c4]);
    float* o = &out[(size_t)dd * HD + c4];
    atomicAdd(o + 0, v.x * alpha);
    atomicAdd(o + 1, v.y * alpha);
    atomicAdd(o + 2, v.z * alpha);
    atomicAdd(o + 3, v.w * alpha);
}

// ================= launcher =================
extern "C" void kernel_launch(void* const* d_in, const int* in_sizes, int n_in,
                              void* d_out, int out_size) {
    const float* feat  = (const float*)d_in[0];
    const float* Wih   = (const float*)d_in[1];
    const float* Whh   = (const float*)d_in[2];
    const float* bih   = (const float*)d_in[3];
    const float* bhh   = (const float*)d_in[4];
    const float* attnw = (const float*)d_in[5];
    const int* mp_idx  = (const int*)d_in[6];
    const int* dst     = (const int*)d_in[7];
    const int E      = in_sizes[7];
    const int nodes  = in_sizes[0] / DF;
    float* out = (float*)d_out;
    const int nd8 = (out_size / HD) * HHn;

    float *pF, *pH, *pGH;
    cudaGetSymbolAddress((void**)&pF,  g_F);
    cudaGetSymbolAddress((void**)&pH,  g_h);
    cudaGetSymbolAddress((void**)&pGH, g_gh);

    zero_kernel<<<2048, 256>>>(out, out_size, nd8);

    // F = features @ W_ih^T + b_ih   (over nodes)
    {
        dim3 grid(G3 / NTW, (nodes + MT - 1) / MT);
        sgemm_bias<DF><<<grid, TPB>>>(feat, Wih, bih, pF, nodes);
    }

    const int ew = (E * (HD / 4) + 255) / 256;   // elementwise grid
    step0_kernel<<<ew, 256>>>(mp_idx, bhh, E);

    dim3 grid512(G3 / NTW, (E + MT - 1) / MT);
    // step 1
    sgemm_bias<HD><<<grid512, TPB>>>(pH, Whh, bhh, pGH, E);
    gates_kernel<<<ew, 256>>>(mp_idx, E, 1);
    // step 2
    sgemm_bias<HD><<<grid512, TPB>>>(pH, Whh, bhh, pGH, E);
    gates_kernel<<<ew, 256>>>(mp_idx, E, 2);

    logit_kernel<<<(E * HHn + 255) / 256, 256>>>(attnw, dst, E);
    finalize_kernel<<<ew, 256>>>(dst, out, E);
}

// round 9
// speedup vs baseline: 3.6157x; 1.5005x over previous
#include <cuda_runtime.h>
#include <cuda_bf16.h>
#include <cstdint>

// ---------------- problem constants ----------------
#define DF    64
#define HHn   8
#define HD    512
#define G3    1536
#define NODES_MAX 100000
#define E_MAX     100000
#define ND_MAX    50000

// ---------------- device scratch ----------------
__device__ float g_F[(size_t)NODES_MAX * G3];          // x@Wih^T + b_ih
__device__ float g_h[(size_t)E_MAX * HD];              // final hidden (fp32)
__device__ __nv_bfloat16 g_Xh[(size_t)NODES_MAX * DF]; // feature splits
__device__ __nv_bfloat16 g_Xl[(size_t)NODES_MAX * DF];
__device__ __nv_bfloat16 g_Ah0[(size_t)E_MAX * HD];    // h splits (ping)
__device__ __nv_bfloat16 g_Al0[(size_t)E_MAX * HD];
__device__ __nv_bfloat16 g_Ah1[(size_t)E_MAX * HD];    // h splits (pong)
__device__ __nv_bfloat16 g_Al1[(size_t)E_MAX * HD];
__device__ __nv_bfloat16 g_Bhh[(size_t)G3 * G3];       // Whh packed [Bh|Bl|Bh]
__device__ __nv_bfloat16 g_Bih[(size_t)G3 * (3 * DF)]; // Wih packed
__device__ float g_aexp[(size_t)E_MAX * HHn];
__device__ float g_asum[(size_t)ND_MAX * HHn];

// ---------------- helpers ----------------
__device__ __forceinline__ uint32_t smem_u32(const void* p) {
    uint32_t a;
    asm("{ .reg .u64 t; cvta.to.shared.u64 t, %1; cvt.u32.u64 %0, t; }"
        : "=r"(a) : "l"(p));
    return a;
}
__device__ __forceinline__ void cp16(uint32_t s, const void* g) {
    asm volatile("cp.async.cg.shared.global [%0], [%1], 16;" :: "r"(s), "l"(g));
}
__device__ __forceinline__ void cp_commit() {
    asm volatile("cp.async.commit_group;" ::: "memory");
}
template<int N>
__device__ __forceinline__ void cp_wait() {
    asm volatile("cp.async.wait_group %0;" :: "n"(N) : "memory");
}
__device__ __forceinline__ void ldsm4(uint32_t& r0, uint32_t& r1, uint32_t& r2,
                                      uint32_t& r3, uint32_t addr) {
    asm volatile("ldmatrix.sync.aligned.m8n8.x4.shared.b16 {%0,%1,%2,%3}, [%4];"
                 : "=r"(r0), "=r"(r1), "=r"(r2), "=r"(r3) : "r"(addr));
}
__device__ __forceinline__ void mma16816(float* c, const uint32_t* a,
                                         uint32_t b0, uint32_t b1) {
    asm volatile("mma.sync.aligned.m16n8k16.row.col.f32.bf16.bf16.f32 "
                 "{%0,%1,%2,%3}, {%4,%5,%6,%7}, {%8,%9}, {%0,%1,%2,%3};"
                 : "+f"(c[0]), "+f"(c[1]), "+f"(c[2]), "+f"(c[3])
                 : "r"(a[0]), "r"(a[1]), "r"(a[2]), "r"(a[3]), "r"(b0), "r"(b1));
}
__device__ __forceinline__ float2 ld2f(const float* p) { return *reinterpret_cast<const float2*>(p); }
__device__ __forceinline__ float4 ld4(const float* p)  { return *reinterpret_cast<const float4*>(p); }
__device__ __forceinline__ float sigmf(float x) { return __fdividef(1.0f, 1.0f + __expf(-x)); }
__device__ __forceinline__ float tanhfast(float x) {
    return 1.0f - __fdividef(2.0f, __expf(2.0f * x) + 1.0f);
}
__device__ __forceinline__ float gru_one(float fr, float gr, float fz, float gz,
                                         float fn, float gn, float hp) {
    float r = sigmf(fr + gr);
    float z = sigmf(fz + gz);
    float n = tanhfast(fn + r * gn);
    return n + z * (hp - n);
}
__device__ __forceinline__ void split_bf16(float x, unsigned short& hi, unsigned short& lo) {
    __nv_bfloat16 h = __float2bfloat16_rn(x);
    __nv_bfloat16 l = __float2bfloat16_rn(x - __bfloat162float(h));
    hi = __bfloat16_as_ushort(h);
    lo = __bfloat16_as_ushort(l);
}
__device__ __forceinline__ float bf2f(unsigned short u) {
    return __bfloat162float(__ushort_as_bfloat16(u));
}

// ================= HMMA GEMM + fused GRU epilogue =================
// C tile: 128 rows x 64 cols x 3 gates.  K' = 3*KREG (bf16 3-way split).
// A' = [Ah|Ah|Al] (rows, K'), B' = packed [Bh|Bl|Bh] rows [1536][K'].
// MODE 0: +bias -> fp32 outF[M,1536]; MODE 1: GRU -> bf16 splits;
// MODE 2: GRU -> fp32 h[M,512].
#define HSTRIDE 136               // smem row stride in bf16 halves (272 B)
#define ABUF    (128 * 272)
#define BBUF    (192 * 272)
#define BUFSZ   (ABUF + BBUF)
#define SMEMSZ  (2 * BUFSZ)

template<int KREG, int MODE>
__global__ void __launch_bounds__(256, 1)
hmma_gemm(const __nv_bfloat16* __restrict__ Ah,
          const __nv_bfloat16* __restrict__ Al,
          const __nv_bfloat16* __restrict__ Bp,
          const float* __restrict__ bias,
          const int* __restrict__ mp,
          float* __restrict__ outF,
          __nv_bfloat16* __restrict__ oAh,
          __nv_bfloat16* __restrict__ oAl,
          int M, int t)
{
    constexpr int KTOT  = 3 * KREG;
    constexpr int KTILE = (KREG == 64) ? 64 : 128;
    constexpr int T     = KTOT / KTILE;
    constexpr int CPR   = KTILE / 8;            // 16B chunks per row
    constexpr int ACH   = 128 * CPR;
    constexpr int TCH   = 320 * CPR;            // A(128)+B(192) rows

    extern __shared__ char sm[];
    const uint32_t sbase = smem_u32(sm);

    const int tid  = threadIdx.x;
    const int wid  = tid >> 5;
    const int lane = tid & 31;
    const int nb   = blockIdx.x * 64;           // col block within gate
    const int mb   = blockIdx.y * 128;

    const int wq = wid >> 1;                    // m quarter (0..3)
    const int wn = wid & 1;                     // n half    (0..1)

    float acc[3][2][4][4];
    #pragma unroll
    for (int g = 0; g < 3; ++g)
        #pragma unroll
        for (int i = 0; i < 2; ++i)
            #pragma unroll
            for (int j = 0; j < 4; ++j)
                #pragma unroll
                for (int c = 0; c < 4; ++c) acc[g][i][j][c] = 0.f;

    // ---- staging helper (cp.async) ----
    auto stage = [&](int kt) {
        const int buf = kt & 1;
        const int region = (kt * KTILE) / KREG;
        const int acol   = kt * KTILE - region * KREG;
        const __nv_bfloat16* As = (region == 2) ? Al : Ah;
        const uint32_t ab = sbase + buf * BUFSZ;
        #pragma unroll 4
        for (int i = tid; i < TCH; i += 256) {
            if (i < ACH) {
                int row = i / CPR, c = i - row * CPR;
                int gr = mb + row; if (gr >= M) gr = M - 1;
                cp16(ab + row * 272 + c * 16, &As[(size_t)gr * KREG + acol + c * 8]);
            } else {
                int j = i - ACH;
                int lr = j / CPR, c = j - lr * CPR;
                int grow = (lr >> 6) * 512 + nb + (lr & 63);
                cp16(ab + ABUF + lr * 272 + c * 16,
                     &Bp[(size_t)grow * KTOT + kt * KTILE + c * 8]);
            }
        }
        cp_commit();
    };

    stage(0);
    for (int kt = 0; kt < T; ++kt) {
        if (kt + 1 < T) stage(kt + 1);
        if (kt + 1 < T) cp_wait<1>(); else cp_wait<0>();
        __syncthreads();

        const uint32_t ab = sbase + (kt & 1) * BUFSZ;
        const uint32_t bb = ab + ABUF;
        const int lr16 = lane & 15;
        const int koff = (lane >> 4) << 3;      // +8 halves for hi lanes

        #pragma unroll
        for (int kk = 0; kk < KTILE; kk += 16) {
            uint32_t af[2][4];
            #pragma unroll
            for (int ma = 0; ma < 2; ++ma) {
                uint32_t a = ab + ((wq * 32 + ma * 16 + lr16) * HSTRIDE + kk + koff) * 2;
                ldsm4(af[ma][0], af[ma][1], af[ma][2], af[ma][3], a);
            }
            #pragma unroll
            for (int g = 0; g < 3; ++g) {
                #pragma unroll
                for (int np = 0; np < 2; ++np) {
                    uint32_t b0, b1, b2, b3;
                    uint32_t a = bb + ((g * 64 + wn * 32 + np * 16 + lr16) * HSTRIDE
                                       + kk + koff) * 2;
                    ldsm4(b0, b1, b2, b3, a);
                    #pragma unroll
                    for (int ma = 0; ma < 2; ++ma) {
                        mma16816(acc[g][ma][np * 2 + 0], af[ma], b0, b2);
                        mma16816(acc[g][ma][np * 2 + 1], af[ma], b1, b3);
                    }
                }
            }
        }
        __syncthreads();
    }

    // ---- epilogue ----
    const int gq  = lane >> 2;                 // group id
    const int tig = lane & 3;
    int nodes4[2][2];
    if (MODE != 0) {
        #pragma unroll
        for (int ma = 0; ma < 2; ++ma)
            #pragma unroll
            for (int p = 0; p < 2; ++p) {
                int m = mb + wq * 32 + ma * 16 + gq + p * 8;
                nodes4[ma][p] = (m < M) ? mp[m * 3 + t] : 0;
            }
    }
    #pragma unroll
    for (int ma = 0; ma < 2; ++ma) {
        #pragma unroll
        for (int p = 0; p < 2; ++p) {
            const int m = mb + wq * 32 + ma * 16 + gq + p * 8;
            if (m >= M) continue;
            #pragma unroll
            for (int na = 0; na < 4; ++na) {
                const int j = nb + wn * 32 + na * 8 + tig * 2;
                float vr0 = acc[0][ma][na][p * 2],     vr1 = acc[0][ma][na][p * 2 + 1];
                float vz0 = acc[1][ma][na][p * 2],     vz1 = acc[1][ma][na][p * 2 + 1];
                float vn0 = acc[2][ma][na][p * 2],     vn1 = acc[2][ma][na][p * 2 + 1];
                float2 br = ld2f(&bias[j]);
                float2 bz = ld2f(&bias[512 + j]);
                float2 bn = ld2f(&bias[1024 + j]);
                if (MODE == 0) {
                    *reinterpret_cast<float2*>(&outF[(size_t)m * G3 + j]) =
                        make_float2(vr0 + br.x, vr1 + br.y);
                    *reinterpret_cast<float2*>(&outF[(size_t)m * G3 + 512 + j]) =
                        make_float2(vz0 + bz.x, vz1 + bz.y);
                    *reinterpret_cast<float2*>(&outF[(size_t)m * G3 + 1024 + j]) =
                        make_float2(vn0 + bn.x, vn1 + bn.y);
                } else {
                    const float* Fp = &g_F[(size_t)nodes4[ma][p] * G3];
                    float2 fr = ld2f(&Fp[j]);
                    float2 fz = ld2f(&Fp[512 + j]);
                    float2 fn = ld2f(&Fp[1024 + j]);
                    ushort2 uh = *reinterpret_cast<const ushort2*>(&Ah[(size_t)m * HD + j]);
                    ushort2 ul = *reinterpret_cast<const ushort2*>(&Al[(size_t)m * HD + j]);
                    float h0 = gru_one(fr.x, vr0 + br.x, fz.x, vz0 + bz.x,
                                       fn.x, vn0 + bn.x, bf2f(uh.x) + bf2f(ul.x));
                    float h1 = gru_one(fr.y, vr1 + br.y, fz.y, vz1 + bz.y,
                                       fn.y, vn1 + bn.y, bf2f(uh.y) + bf2f(ul.y));
                    if (MODE == 1) {
                        ushort2 oh, ol;
                        split_bf16(h0, oh.x, ol.x);
                        split_bf16(h1, oh.y, ol.y);
                        *reinterpret_cast<ushort2*>(&oAh[(size_t)m * HD + j]) = oh;
                        *reinterpret_cast<ushort2*>(&oAl[(size_t)m * HD + j]) = ol;
                    } else {
                        *reinterpret_cast<float2*>(&outF[(size_t)m * HD + j]) =
                            make_float2(h0, h1);
                    }
                }
            }
        }
    }
}

// ================= elementwise kernels =================
__global__ void zero_kernel(float* __restrict__ out, int nOut, int nSum) {
    int stride = gridDim.x * blockDim.x;
    int i0 = blockIdx.x * blockDim.x + threadIdx.x;
    for (int i = i0; i < nOut; i += stride) out[i] = 0.0f;
    for (int i = i0; i < nSum; i += stride) g_asum[i] = 0.0f;
}

// build bf16 splits of features + packed split weights [Bh|Bl|Bh]
__global__ void split_kernel(const float* __restrict__ feat,
                             const float* __restrict__ Whh,
                             const float* __restrict__ Wih, int nodes) {
    int stride = gridDim.x * blockDim.x;
    int i0 = blockIdx.x * blockDim.x + threadIdx.x;
    for (int i = i0; i < nodes * DF; i += stride) {
        unsigned short hi, lo;
        split_bf16(feat[i], hi, lo);
        g_Xh[i] = __ushort_as_bfloat16(hi);
        g_Xl[i] = __ushort_as_bfloat16(lo);
    }
    for (int i = i0; i < G3 * HD; i += stride) {
        int n = i >> 9, k = i & 511;
        unsigned short hi, lo;
        split_bf16(Whh[i], hi, lo);
        size_t b = (size_t)n * G3;
        g_Bhh[b + k]        = __ushort_as_bfloat16(hi);
        g_Bhh[b + 512 + k]  = __ushort_as_bfloat16(lo);
        g_Bhh[b + 1024 + k] = __ushort_as_bfloat16(hi);
    }
    for (int i = i0; i < G3 * DF; i += stride) {
        int n = i >> 6, k = i & 63;
        unsigned short hi, lo;
        split_bf16(Wih[i], hi, lo);
        size_t b = (size_t)n * (3 * DF);
        g_Bih[b + k]       = __ushort_as_bfloat16(hi);
        g_Bih[b + 64 + k]  = __ushort_as_bfloat16(lo);
        g_Bih[b + 128 + k] = __ushort_as_bfloat16(hi);
    }
}

// step 0: h0 = 0 -> gh = b_hh; h1 = gru(F[node0], b_hh); write bf16 splits
__global__ void step0_kernel(const int* __restrict__ mp,
                             const float* __restrict__ bhh, int E) {
    int i = blockIdx.x * blockDim.x + threadIdx.x;
    if (i >= E * (HD / 4)) return;
    int e = i >> 7, c4 = (i & 127) << 2;
    int node = mp[e * 3];
    const float* Fp = &g_F[(size_t)node * G3];
    float4 fr = ld4(Fp + c4), fz = ld4(Fp + 512 + c4), fn = ld4(Fp + 1024 + c4);
    float4 br = ld4(bhh + c4), bz = ld4(bhh + 512 + c4), bn = ld4(bhh + 1024 + c4);
    float h0 = gru_one(fr.x, br.x, fz.x, bz.x, fn.x, bn.x, 0.f);
    float h1 = gru_one(fr.y, br.y, fz.y, bz.y, fn.y, bn.y, 0.f);
    float h2 = gru_one(fr.z, br.z, fz.z, bz.z, fn.z, bn.z, 0.f);
    float h3 = gru_one(fr.w, br.w, fz.w, bz.w, fn.w, bn.w, 0.f);
    ushort4 oh, ol;
    split_bf16(h0, oh.x, ol.x); split_bf16(h1, oh.y, ol.y);
    split_bf16(h2, oh.z, ol.z); split_bf16(h3, oh.w, ol.w);
    *reinterpret_cast<ushort4*>(&g_Ah0[(size_t)e * HD + c4]) = oh;
    *reinterpret_cast<ushort4*>(&g_Al0[(size_t)e * HD + c4]) = ol;
}

// attention logits + exp + segment-sum
__global__ void logit_kernel(const float* __restrict__ attnw,
                             const int* __restrict__ dst, int E) {
    int gid = blockIdx.x * blockDim.x + threadIdx.x;
    if (gid >= E * HHn) return;
    int e = gid >> 3, hh = gid & 7;
    const float* hp = &g_h[(size_t)e * HD + hh * 64];
    const float* ap = &attnw[hh * 64];
    float s = 0.f;
    #pragma unroll
    for (int k = 0; k < 16; ++k) {
        float4 hv = ld4(hp + k * 4);
        float4 av = ld4(ap + k * 4);
        s += hv.x * av.x + hv.y * av.y + hv.z * av.z + hv.w * av.w;
    }
    float a  = s > 0.f ? s : 0.01f * s;
    float ex = __expf(a);    // logits bounded; no max-shift needed (validated R5-R7)
    g_aexp[gid] = ex;
    atomicAdd(&g_asum[(size_t)dst[e] * HHn + hh], ex);
}

// alpha scale + scatter-sum into output
__global__ void finalize_kernel(const int* __restrict__ dst,
                                float* __restrict__ out, int E) {
    int i = blockIdx.x * blockDim.x + threadIdx.x;
    if (i >= E * (HD / 4)) return;
    int e = i >> 7, c4 = (i & 127) << 2;
    int hh = c4 >> 6;
    int dd = dst[e];
    float alpha = __fdividef(g_aexp[e * HHn + hh], g_asum[(size_t)dd * HHn + hh]);
    float4 v = ld4(&g_h[(size_t)e * HD + c4]);
    float* o = &out[(size_t)dd * HD + c4];
    atomicAdd(o + 0, v.x * alpha);
    atomicAdd(o + 1, v.y * alpha);
    atomicAdd(o + 2, v.z * alpha);
    atomicAdd(o + 3, v.w * alpha);
}

// ================= launcher =================
extern "C" void kernel_launch(void* const* d_in, const int* in_sizes, int n_in,
                              void* d_out, int out_size) {
    const float* feat  = (const float*)d_in[0];
    const float* Wih   = (const float*)d_in[1];
    const float* Whh   = (const float*)d_in[2];
    const float* bih   = (const float*)d_in[3];
    const float* bhh   = (const float*)d_in[4];
    const float* attnw = (const float*)d_in[5];
    const int* mp_idx  = (const int*)d_in[6];
    const int* dst     = (const int*)d_in[7];
    const int E     = in_sizes[7];
    const int nodes = in_sizes[0] / DF;
    float* out = (float*)d_out;
    const int nd8 = (out_size / HD) * HHn;

    float *pF, *pH;
    __nv_bfloat16 *pXh, *pXl, *pAh0, *pAl0, *pAh1, *pAl1, *pBhh, *pBih;
    cudaGetSymbolAddress((void**)&pF,   g_F);
    cudaGetSymbolAddress((void**)&pH,   g_h);
    cudaGetSymbolAddress((void**)&pXh,  g_Xh);
    cudaGetSymbolAddress((void**)&pXl,  g_Xl);
    cudaGetSymbolAddress((void**)&pAh0, g_Ah0);
    cudaGetSymbolAddress((void**)&pAl0, g_Al0);
    cudaGetSymbolAddress((void**)&pAh1, g_Ah1);
    cudaGetSymbolAddress((void**)&pAl1, g_Al1);
    cudaGetSymbolAddress((void**)&pBhh, g_Bhh);
    cudaGetSymbolAddress((void**)&pBih, g_Bih);

    cudaFuncSetAttribute(hmma_gemm<DF, 0>, cudaFuncAttributeMaxDynamicSharedMemorySize, SMEMSZ);
    cudaFuncSetAttribute(hmma_gemm<HD, 1>, cudaFuncAttributeMaxDynamicSharedMemorySize, SMEMSZ);
    cudaFuncSetAttribute(hmma_gemm<HD, 2>, cudaFuncAttributeMaxDynamicSharedMemorySize, SMEMSZ);

    zero_kernel<<<2048, 256>>>(out, out_size, nd8);
    split_kernel<<<2048, 256>>>(feat, Whh, Wih, nodes);

    // F = x @ Wih^T + b_ih  over nodes
    dim3 gF(8, (nodes + 127) / 128);
    hmma_gemm<DF, 0><<<gF, 256, SMEMSZ>>>(pXh, pXl, pBih, bih, nullptr,
                                          pF, nullptr, nullptr, nodes, 0);

    const int ew = (E * (HD / 4) + 255) / 256;
    step0_kernel<<<ew, 256>>>(mp_idx, bhh, E);

    dim3 gE(8, (E + 127) / 128);
    // step 1: gh = h0@Whh^T + b_hh, fused gates -> splits (pong)
    hmma_gemm<HD, 1><<<gE, 256, SMEMSZ>>>(pAh0, pAl0, pBhh, bhh, mp_idx,
                                          nullptr, pAh1, pAl1, E, 1);
    // step 2: fused gates -> final h fp32
    hmma_gemm<HD, 2><<<gE, 256, SMEMSZ>>>(pAh1, pAl1, pBhh, bhh, mp_idx,
                                          pH, nullptr, nullptr, E, 2);

    logit_kernel<<<(E * HHn + 255) / 256, 256>>>(attnw, dst, E);
    finalize_kernel<<<ew, 256>>>(dst, out, E);
}

// round 10
// speedup vs baseline: 4.6956x; 1.2987x over previous
#include <cuda_runtime.h>
#include <cuda_fp16.h>
#include <cstdint>

// ---------------- problem constants ----------------
#define DF    64
#define HHn   8
#define HD    512
#define G3    1536
#define NODES_MAX 100000
#define E_MAX     100000
#define ND_MAX    50000

// ---------------- device scratch ----------------
__device__ float g_F[(size_t)NODES_MAX * G3];     // x@Wih^T + b_ih (fp32)
__device__ float g_h[(size_t)E_MAX * HD];         // final hidden (fp32)
__device__ __half g_Xh[(size_t)NODES_MAX * DF];   // feature splits (fp16)
__device__ __half g_Xl[(size_t)NODES_MAX * DF];
__device__ __half g_Ah0[(size_t)E_MAX * HD];      // h splits (ping)
__device__ __half g_Al0[(size_t)E_MAX * HD];
__device__ __half g_Ah1[(size_t)E_MAX * HD];      // h splits (pong)
__device__ __half g_Al1[(size_t)E_MAX * HD];
__device__ __half g_Bhh[(size_t)G3 * HD];         // fl16(Whh) [1536][512] (1.5 MB)
__device__ __half g_Bih[(size_t)G3 * (3 * DF)];   // Wih packed [Wh|Wl|Wh] fp16
__device__ float g_aexp[(size_t)E_MAX * HHn];
__device__ float g_asum[(size_t)ND_MAX * HHn];

// ---------------- helpers ----------------
__device__ __forceinline__ uint32_t smem_u32(const void* p) {
    uint32_t a;
    asm("{ .reg .u64 t; cvta.to.shared.u64 t, %1; cvt.u32.u64 %0, t; }"
        : "=r"(a) : "l"(p));
    return a;
}
__device__ __forceinline__ void cp16(uint32_t s, const void* g) {
    asm volatile("cp.async.cg.shared.global [%0], [%1], 16;" :: "r"(s), "l"(g));
}
__device__ __forceinline__ void cp_commit() {
    asm volatile("cp.async.commit_group;" ::: "memory");
}
template<int N>
__device__ __forceinline__ void cp_wait() {
    asm volatile("cp.async.wait_group %0;" :: "n"(N) : "memory");
}
__device__ __forceinline__ void ldsm4(uint32_t& r0, uint32_t& r1, uint32_t& r2,
                                      uint32_t& r3, uint32_t addr) {
    asm volatile("ldmatrix.sync.aligned.m8n8.x4.shared.b16 {%0,%1,%2,%3}, [%4];"
                 : "=r"(r0), "=r"(r1), "=r"(r2), "=r"(r3) : "r"(addr));
}
__device__ __forceinline__ void mma16816(float* c, const uint32_t* a,
                                         uint32_t b0, uint32_t b1) {
    asm volatile("mma.sync.aligned.m16n8k16.row.col.f32.f16.f16.f32 "
                 "{%0,%1,%2,%3}, {%4,%5,%6,%7}, {%8,%9}, {%0,%1,%2,%3};"
                 : "+f"(c[0]), "+f"(c[1]), "+f"(c[2]), "+f"(c[3])
                 : "r"(a[0]), "r"(a[1]), "r"(a[2]), "r"(a[3]), "r"(b0), "r"(b1));
}
__device__ __forceinline__ float2 ld2f(const float* p) { return *reinterpret_cast<const float2*>(p); }
__device__ __forceinline__ float4 ld4(const float* p)  { return *reinterpret_cast<const float4*>(p); }
__device__ __forceinline__ float sigmf(float x) { return __fdividef(1.0f, 1.0f + __expf(-x)); }
__device__ __forceinline__ float tanhfast(float x) {
    return 1.0f - __fdividef(2.0f, __expf(2.0f * x) + 1.0f);
}
__device__ __forceinline__ float gru_one(float fr, float gr, float fz, float gz,
                                         float fn, float gn, float hp) {
    float r = sigmf(fr + gr);
    float z = sigmf(fz + gz);
    float n = tanhfast(fn + r * gn);
    return n + z * (hp - n);
}
__device__ __forceinline__ void split_f16(float x, unsigned short& hi, unsigned short& lo) {
    __half h = __float2half_rn(x);
    __half l = __float2half_rn(x - __half2float(h));
    hi = __half_as_ushort(h);
    lo = __half_as_ushort(l);
}
__device__ __forceinline__ float h2f(unsigned short u) {
    return __half2float(__ushort_as_half(u));
}

// ================= HMMA GEMM + fused GRU epilogue =================
// C tile: 128 rows x 64 cols x 3 gates.
// MODE 0 (F-GEMM): K' = 192 = [Xh|Xh|Xl] x [Wh|Wl|Wl-pack] (3-term, exact-ish);
//                  epilogue: +bias -> fp32 outF[M,1536].
// MODE 1/2 (steps): K' = 1024 = [Ah|Al] x [Bh|Bh] (2-term, a*fl16(b));
//                  epilogue: GRU gates; MODE1 -> fp16 splits, MODE2 -> fp32 h.
template<int MODE>
__global__ void __launch_bounds__(256, 1)
hmma_gemm(const __half* __restrict__ Ah,
          const __half* __restrict__ Al,
          const __half* __restrict__ Bp,
          const float* __restrict__ bias,
          const int* __restrict__ mp,
          float* __restrict__ outF,
          __half* __restrict__ oAh,
          __half* __restrict__ oAl,
          int M, int t)
{
    constexpr int KTILE = (MODE == 0) ? 64 : 128;
    constexpr int T     = (MODE == 0) ? 3 : 8;
    constexpr int KB    = (MODE == 0) ? 192 : 512;  // B row length (halves)
    constexpr int KA    = (MODE == 0) ? 64 : 512;   // A row length (halves)
    constexpr int HS    = KTILE + 8;                // smem row stride (halves)
    constexpr int CPR   = KTILE / 8;                // 16B chunks per row
    constexpr int ACH   = 128 * CPR;
    constexpr int TCH   = 320 * CPR;
    constexpr int ABUFB = 128 * HS * 2;
    constexpr int BUFB  = 320 * HS * 2;

    extern __shared__ char sm[];
    const uint32_t sbase = smem_u32(sm);

    const int tid  = threadIdx.x;
    const int wid  = tid >> 5;
    const int lane = tid & 31;
    const int nb   = blockIdx.x * 64;           // col block within gate
    const int mb   = blockIdx.y * 128;

    const int wq = wid >> 1;                    // m quarter (0..3)
    const int wn = wid & 1;                     // n half    (0..1)

    float acc[3][2][4][4];
    #pragma unroll
    for (int g = 0; g < 3; ++g)
        #pragma unroll
        for (int i = 0; i < 2; ++i)
            #pragma unroll
            for (int j = 0; j < 4; ++j)
                #pragma unroll
                for (int c = 0; c < 4; ++c) acc[g][i][j][c] = 0.f;

    // ---- staging (cp.async) ----
    auto stage = [&](int kt) {
        const __half* As;
        int acol, bcol;
        if (MODE == 0) { As = (kt == 2) ? Al : Ah; acol = 0;              bcol = kt * 64; }
        else           { As = (kt >= 4) ? Al : Ah; acol = (kt & 3) * 128; bcol = (kt & 3) * 128; }
        const uint32_t ab = sbase + (kt & 1) * BUFB;
        #pragma unroll 4
        for (int i = tid; i < TCH; i += 256) {
            if (i < ACH) {
                int row = i / CPR, c = i - row * CPR;
                int gr = mb + row; if (gr >= M) gr = M - 1;
                cp16(ab + (row * HS + c * 8) * 2, &As[(size_t)gr * KA + acol + c * 8]);
            } else {
                int j = i - ACH;
                int lr = j / CPR, c = j - lr * CPR;
                int grow = (lr >> 6) * 512 + nb + (lr & 63);
                cp16(ab + ABUFB + (lr * HS + c * 8) * 2,
                     &Bp[(size_t)grow * KB + bcol + c * 8]);
            }
        }
        cp_commit();
    };

    stage(0);
    for (int kt = 0; kt < T; ++kt) {
        if (kt + 1 < T) stage(kt + 1);
        if (kt + 1 < T) cp_wait<1>(); else cp_wait<0>();
        __syncthreads();

        const uint32_t ab = sbase + (kt & 1) * BUFB;
        const uint32_t bb = ab + ABUFB;
        const int lr16 = lane & 15;
        const int koff = (lane >> 4) << 3;

        #pragma unroll
        for (int kk = 0; kk < KTILE; kk += 16) {
            uint32_t af[2][4];
            #pragma unroll
            for (int ma = 0; ma < 2; ++ma) {
                uint32_t a = ab + ((wq * 32 + ma * 16 + lr16) * HS + kk + koff) * 2;
                ldsm4(af[ma][0], af[ma][1], af[ma][2], af[ma][3], a);
            }
            #pragma unroll
            for (int g = 0; g < 3; ++g) {
                #pragma unroll
                for (int np = 0; np < 2; ++np) {
                    uint32_t b0, b1, b2, b3;
                    uint32_t a = bb + ((g * 64 + wn * 32 + np * 16 + lr16) * HS
                                       + kk + koff) * 2;
                    ldsm4(b0, b1, b2, b3, a);
                    #pragma unroll
                    for (int ma = 0; ma < 2; ++ma) {
                        mma16816(acc[g][ma][np * 2 + 0], af[ma], b0, b2);
                        mma16816(acc[g][ma][np * 2 + 1], af[ma], b1, b3);
                    }
                }
            }
        }
        __syncthreads();
    }

    // ---- epilogue ----
    const int gq  = lane >> 2;
    const int tig = lane & 3;
    int nodes4[2][2];
    if (MODE != 0) {
        #pragma unroll
        for (int ma = 0; ma < 2; ++ma)
            #pragma unroll
            for (int p = 0; p < 2; ++p) {
                int m = mb + wq * 32 + ma * 16 + gq + p * 8;
                nodes4[ma][p] = (m < M) ? mp[m * 3 + t] : 0;
            }
    }
    #pragma unroll
    for (int ma = 0; ma < 2; ++ma) {
        #pragma unroll
        for (int p = 0; p < 2; ++p) {
            const int m = mb + wq * 32 + ma * 16 + gq + p * 8;
            if (m >= M) continue;
            #pragma unroll
            for (int na = 0; na < 4; ++na) {
                const int j = nb + wn * 32 + na * 8 + tig * 2;
                float vr0 = acc[0][ma][na][p * 2], vr1 = acc[0][ma][na][p * 2 + 1];
                float vz0 = acc[1][ma][na][p * 2], vz1 = acc[1][ma][na][p * 2 + 1];
                float vn0 = acc[2][ma][na][p * 2], vn1 = acc[2][ma][na][p * 2 + 1];
                float2 br = ld2f(&bias[j]);
                float2 bz = ld2f(&bias[512 + j]);
                float2 bn = ld2f(&bias[1024 + j]);
                if (MODE == 0) {
                    *reinterpret_cast<float2*>(&outF[(size_t)m * G3 + j]) =
                        make_float2(vr0 + br.x, vr1 + br.y);
                    *reinterpret_cast<float2*>(&outF[(size_t)m * G3 + 512 + j]) =
                        make_float2(vz0 + bz.x, vz1 + bz.y);
                    *reinterpret_cast<float2*>(&outF[(size_t)m * G3 + 1024 + j]) =
                        make_float2(vn0 + bn.x, vn1 + bn.y);
                } else {
                    const float* Fp = &g_F[(size_t)nodes4[ma][p] * G3];
                    float2 fr = ld2f(&Fp[j]);
                    float2 fz = ld2f(&Fp[512 + j]);
                    float2 fn = ld2f(&Fp[1024 + j]);
                    ushort2 uh = *reinterpret_cast<const ushort2*>(&Ah[(size_t)m * HD + j]);
                    ushort2 ul = *reinterpret_cast<const ushort2*>(&Al[(size_t)m * HD + j]);
                    float h0 = gru_one(fr.x, vr0 + br.x, fz.x, vz0 + bz.x,
                                       fn.x, vn0 + bn.x, h2f(uh.x) + h2f(ul.x));
                    float h1 = gru_one(fr.y, vr1 + br.y, fz.y, vz1 + bz.y,
                                       fn.y, vn1 + bn.y, h2f(uh.y) + h2f(ul.y));
                    if (MODE == 1) {
                        ushort2 oh, ol;
                        split_f16(h0, oh.x, ol.x);
                        split_f16(h1, oh.y, ol.y);
                        *reinterpret_cast<ushort2*>(&oAh[(size_t)m * HD + j]) = oh;
                        *reinterpret_cast<ushort2*>(&oAl[(size_t)m * HD + j]) = ol;
                    } else {
                        *reinterpret_cast<float2*>(&outF[(size_t)m * HD + j]) =
                            make_float2(h0, h1);
                    }
                }
            }
        }
    }
}

// ================= elementwise kernels =================
__global__ void zero_kernel(float* __restrict__ out, int nOut, int nSum) {
    int stride = gridDim.x * blockDim.x;
    int i0 = blockIdx.x * blockDim.x + threadIdx.x;
    for (int i = i0; i < nOut; i += stride) out[i] = 0.0f;
    for (int i = i0; i < nSum; i += stride) g_asum[i] = 0.0f;
}

// fp16 splits of features; Whh -> fl16 single copy; Wih packed [Wh|Wl|Wh]
__global__ void split_kernel(const float* __restrict__ feat,
                             const float* __restrict__ Whh,
                             const float* __restrict__ Wih, int nodes) {
    int stride = gridDim.x * blockDim.x;
    int i0 = blockIdx.x * blockDim.x + threadIdx.x;
    for (int i = i0; i < nodes * DF; i += stride) {
        unsigned short hi, lo;
        split_f16(feat[i], hi, lo);
        g_Xh[i] = __ushort_as_half(hi);
        g_Xl[i] = __ushort_as_half(lo);
    }
    for (int i = i0; i < G3 * HD; i += stride)
        g_Bhh[i] = __float2half_rn(Whh[i]);
    for (int i = i0; i < G3 * DF; i += stride) {
        int n = i >> 6, k = i & 63;
        unsigned short hi, lo;
        split_f16(Wih[i], hi, lo);
        size_t b = (size_t)n * (3 * DF);
        g_Bih[b + k]       = __ushort_as_half(hi);
        g_Bih[b + 64 + k]  = __ushort_as_half(lo);
        g_Bih[b + 128 + k] = __ushort_as_half(hi);
    }
}

// step 0: h0 = 0 -> gh = b_hh; h1 = gru(F[node0], b_hh); write fp16 splits
__global__ void step0_kernel(const int* __restrict__ mp,
                             const float* __restrict__ bhh, int E) {
    int i = blockIdx.x * blockDim.x + threadIdx.x;
    if (i >= E * (HD / 4)) return;
    int e = i >> 7, c4 = (i & 127) << 2;
    int node = mp[e * 3];
    const float* Fp = &g_F[(size_t)node * G3];
    float4 fr = ld4(Fp + c4), fz = ld4(Fp + 512 + c4), fn = ld4(Fp + 1024 + c4);
    float4 br = ld4(bhh + c4), bz = ld4(bhh + 512 + c4), bn = ld4(bhh + 1024 + c4);
    float h0 = gru_one(fr.x, br.x, fz.x, bz.x, fn.x, bn.x, 0.f);
    float h1 = gru_one(fr.y, br.y, fz.y, bz.y, fn.y, bn.y, 0.f);
    float h2 = gru_one(fr.z, br.z, fz.z, bz.z, fn.z, bn.z, 0.f);
    float h3 = gru_one(fr.w, br.w, fz.w, bz.w, fn.w, bn.w, 0.f);
    ushort4 oh, ol;
    split_f16(h0, oh.x, ol.x); split_f16(h1, oh.y, ol.y);
    split_f16(h2, oh.z, ol.z); split_f16(h3, oh.w, ol.w);
    *reinterpret_cast<ushort4*>(&g_Ah0[(size_t)e * HD + c4]) = oh;
    *reinterpret_cast<ushort4*>(&g_Al0[(size_t)e * HD + c4]) = ol;
}

// attention logits + exp + segment-sum
__global__ void logit_kernel(const float* __restrict__ attnw,
                             const int* __restrict__ dst, int E) {
    int gid = blockIdx.x * blockDim.x + threadIdx.x;
    if (gid >= E * HHn) return;
    int e = gid >> 3, hh = gid & 7;
    const float* hp = &g_h[(size_t)e * HD + hh * 64];
    const float* ap = &attnw[hh * 64];
    float s = 0.f;
    #pragma unroll
    for (int k = 0; k < 16; ++k) {
        float4 hv = ld4(hp + k * 4);
        float4 av = ld4(ap + k * 4);
        s += hv.x * av.x + hv.y * av.y + hv.z * av.z + hv.w * av.w;
    }
    float a  = s > 0.f ? s : 0.01f * s;
    float ex = __expf(a);    // logits bounded; no max-shift needed (validated R5-R9)
    g_aexp[gid] = ex;
    atomicAdd(&g_asum[(size_t)dst[e] * HHn + hh], ex);
}

// alpha scale + scatter-sum into output
__global__ void finalize_kernel(const int* __restrict__ dst,
                                float* __restrict__ out, int E) {
    int i = blockIdx.x * blockDim.x + threadIdx.x;
    if (i >= E * (HD / 4)) return;
    int e = i >> 7, c4 = (i & 127) << 2;
    int hh = c4 >> 6;
    int dd = dst[e];
    float alpha = __fdividef(g_aexp[e * HHn + hh], g_asum[(size_t)dd * HHn + hh]);
    float4 v = ld4(&g_h[(size_t)e * HD + c4]);
    float* o = &out[(size_t)dd * HD + c4];
    atomicAdd(o + 0, v.x * alpha);
    atomicAdd(o + 1, v.y * alpha);
    atomicAdd(o + 2, v.z * alpha);
    atomicAdd(o + 3, v.w * alpha);
}

// ================= launcher =================
extern "C" void kernel_launch(void* const* d_in, const int* in_sizes, int n_in,
                              void* d_out, int out_size) {
    const float* feat  = (const float*)d_in[0];
    const float* Wih   = (const float*)d_in[1];
    const float* Whh   = (const float*)d_in[2];
    const float* bih   = (const float*)d_in[3];
    const float* bhh   = (const float*)d_in[4];
    const float* attnw = (const float*)d_in[5];
    const int* mp_idx  = (const int*)d_in[6];
    const int* dst     = (const int*)d_in[7];
    const int E     = in_sizes[7];
    const int nodes = in_sizes[0] / DF;
    float* out = (float*)d_out;
    const int nd8 = (out_size / HD) * HHn;

    float *pF, *pH;
    __half *pXh, *pXl, *pAh0, *pAl0, *pAh1, *pAl1, *pBhh, *pBih;
    cudaGetSymbolAddress((void**)&pF,   g_F);
    cudaGetSymbolAddress((void**)&pH,   g_h);
    cudaGetSymbolAddress((void**)&pXh,  g_Xh);
    cudaGetSymbolAddress((void**)&pXl,  g_Xl);
    cudaGetSymbolAddress((void**)&pAh0, g_Ah0);
    cudaGetSymbolAddress((void**)&pAl0, g_Al0);
    cudaGetSymbolAddress((void**)&pAh1, g_Ah1);
    cudaGetSymbolAddress((void**)&pAl1, g_Al1);
    cudaGetSymbolAddress((void**)&pBhh, g_Bhh);
    cudaGetSymbolAddress((void**)&pBih, g_Bih);

    const int smemF = 2 * 320 * (64 + 8) * 2;    // 92160
    const int smemS = 2 * 320 * (128 + 8) * 2;   // 174080
    cudaFuncSetAttribute(hmma_gemm<0>, cudaFuncAttributeMaxDynamicSharedMemorySize, smemF);
    cudaFuncSetAttribute(hmma_gemm<1>, cudaFuncAttributeMaxDynamicSharedMemorySize, smemS);
    cudaFuncSetAttribute(hmma_gemm<2>, cudaFuncAttributeMaxDynamicSharedMemorySize, smemS);

    zero_kernel<<<2048, 256>>>(out, out_size, nd8);
    split_kernel<<<2048, 256>>>(feat, Whh, Wih, nodes);

    // F = x @ Wih^T + b_ih  over nodes (3-term fp16, K'=192)
    dim3 gF(8, (nodes + 127) / 128);
    hmma_gemm<0><<<gF, 256, smemF>>>(pXh, pXl, pBih, bih, nullptr,
                                     pF, nullptr, nullptr, nodes, 0);

    const int ew = (E * (HD / 4) + 255) / 256;
    step0_kernel<<<ew, 256>>>(mp_idx, bhh, E);

    dim3 gE(8, (E + 127) / 128);
    // step 1: gh = h1 @ fl16(Whh)^T + b_hh (2-term), fused gates -> splits
    hmma_gemm<1><<<gE, 256, smemS>>>(pAh0, pAl0, pBhh, bhh, mp_idx,
                                     nullptr, pAh1, pAl1, E, 1);
    // step 2: fused gates -> final h fp32
    hmma_gemm<2><<<gE, 256, smemS>>>(pAh1, pAl1, pBhh, bhh, mp_idx,
                                     pH, nullptr, nullptr, E, 2);

    logit_kernel<<<(E * HHn + 255) / 256, 256>>>(attnw, dst, E);
    finalize_kernel<<<ew, 256>>>(dst, out, E);
}